// round 5
// baseline (speedup 1.0000x reference)
#include <cuda_runtime.h>

// Problem constants (fixed instance)
#define B_ 8
#define C_ 96
#define H_ 224
#define W_ 224
#define BC_ (B_*C_)

// Scratch arena offsets (floats)
#define OFF_C0  ((size_t)0)                            // BC*4*112*112
#define OFF_C1  (OFF_C0 + (size_t)BC_*4*112*112)       // BC*4*56*56
#define OFF_C2  (OFF_C1 + (size_t)BC_*4*56*56)         // BC*4*28*28
#define OFF_LL1 (OFF_C2 + (size_t)BC_*4*28*28)         // BC*112*112
#define OFF_LL2 (OFF_LL1 + (size_t)BC_*112*112)        // BC*56*56
#define ARENA_FLOATS (OFF_LL2 + (size_t)BC_*56*56)

__device__ float g_arena[ARENA_FLOATS];

// ---------------------------------------------------------------------------
// Forward level kernel. Coeff tile 28x28 (divides 112/56/28 exactly -> zero
// grid waste, no bounds checks). 224 threads; conv phase uses 196 threads,
// each a 2x2 coeff quad with a conflict-free float2 register window.
// ---------------------------------------------------------------------------
__global__ __launch_bounds__(224) void fwd_kernel(
    const float* __restrict__ xin, int use_x, size_t in_off,
    int hin, int win,
    const float* __restrict__ wv,   // (4C,5,5)
    const float* __restrict__ sv,   // (4C)
    size_t coeffs_off,              // (BC,4,h,w)
    size_t ll_off, int has_ll)      // (BC,h,w)
{
    const int h = hin >> 1, w = win >> 1;
    const int bz = blockIdx.z;
    const int c  = bz % C_;
    const int oy0 = blockIdx.y * 28, ox0 = blockIdx.x * 28;   // coeff-domain

    __shared__ float sIn[64][66];       // 56*2 + 8 halo; stride 66 (even)
    __shared__ float sSub[4][32][34];   // 28 + 4 halo; stride 34 (even)
    __shared__ float sW[4][25];
    __shared__ float sScale[4];

    const int tid = threadIdx.x;

    if (tid < 100) {
        int s = tid / 25, k = tid % 25;
        sW[s][k] = wv[(c * 4 + s) * 25 + k];
    }
    if (tid < 4) sScale[tid] = sv[c * 4 + tid];

    // load 64x64 input region (coeff halo 2 -> input halo 4), zero-padded
    const int iy0 = 2 * oy0 - 4, ix0 = 2 * ox0 - 4;
    const float* inp = (use_x ? xin : (const float*)(g_arena + in_off))
                       + (size_t)bz * hin * win;
    for (int i = tid; i < 64 * 64; i += 224) {
        int r = i >> 6, cc = i & 63;
        int gy = iy0 + r, gx = ix0 + cc;
        float v = 0.f;
        if (gy >= 0 && gy < hin && gx >= 0 && gx < win) v = inp[(size_t)gy * win + gx];
        sIn[r][cc] = v;
    }
    __syncthreads();

    // haar into shared: 32x32 subband cells, float2 reads (conflict-free)
    for (int i = tid; i < 32 * 32; i += 224) {
        int y = i >> 5, x = i & 31;
        float2 p = *(const float2*)&sIn[2 * y][2 * x];
        float2 q = *(const float2*)&sIn[2 * y + 1][2 * x];
        float a = p.x, b = p.y, cc = q.x, d = q.y;
        sSub[0][y][x] = (a + b + cc + d) * 0.5f;
        sSub[1][y][x] = (a - b + cc - d) * 0.5f;
        sSub[2][y][x] = (a + b - cc - d) * 0.5f;
        sSub[3][y][x] = (a - b - cc + d) * 0.5f;
    }
    __syncthreads();

    if (tid < 196) {
        const int qy = tid / 14, qx = tid % 14;
        const int cy = 2 * qy, cx = 2 * qx;     // local coeff coords (even)
        const int oy = oy0 + cy, ox = ox0 + cx; // global (always in-bounds)

        if (has_ll) {
            float* lp = g_arena + ll_off + (size_t)bz * h * w;
            *(float2*)&lp[(size_t)oy * w + ox]       = *(const float2*)&sSub[0][cy + 2][cx + 2];
            *(float2*)&lp[(size_t)(oy + 1) * w + ox] = *(const float2*)&sSub[0][cy + 3][cx + 2];
        }

        #pragma unroll
        for (int s = 0; s < 4; s++) {
            // 6x6 window as 6x3 float2 (aligned: cx even, stride 34 even)
            float wreg[6][6];
            #pragma unroll
            for (int r = 0; r < 6; r++) {
                float2 p0 = *(const float2*)&sSub[s][cy + r][cx];
                float2 p1 = *(const float2*)&sSub[s][cy + r][cx + 2];
                float2 p2 = *(const float2*)&sSub[s][cy + r][cx + 4];
                wreg[r][0] = p0.x; wreg[r][1] = p0.y;
                wreg[r][2] = p1.x; wreg[r][3] = p1.y;
                wreg[r][4] = p2.x; wreg[r][5] = p2.y;
            }
            float a00 = 0.f, a01 = 0.f, a10 = 0.f, a11 = 0.f;
            #pragma unroll
            for (int ky = 0; ky < 5; ky++)
                #pragma unroll
                for (int kx = 0; kx < 5; kx++) {
                    float wt = sW[s][ky * 5 + kx];
                    a00 = fmaf(wreg[ky][kx],     wt, a00);
                    a01 = fmaf(wreg[ky][kx + 1], wt, a01);
                    a10 = fmaf(wreg[ky + 1][kx],     wt, a10);
                    a11 = fmaf(wreg[ky + 1][kx + 1], wt, a11);
                }
            float sc = sScale[s];
            float* cp = g_arena + coeffs_off + ((size_t)bz * 4 + s) * h * w;
            *(float2*)&cp[(size_t)oy * w + ox]       = make_float2(a00 * sc, a01 * sc);
            *(float2*)&cp[(size_t)(oy + 1) * w + ox] = make_float2(a10 * sc, a11 * sc);
        }
    }
}

// ---------------------------------------------------------------------------
// Final fused: out = dwconv(x, base_w)*scale + bias
//                  + ihaar0( c0 + ihaar1( c1 + ihaar2(c2) ) )
// The whole inverse chain is a pointwise gather (no halos). 32x32 output
// tile, 256 threads, each owns one c0 cell + the matching 2x2 output quad.
// ---------------------------------------------------------------------------
__global__ __launch_bounds__(256) void final_kernel(
    const float* __restrict__ x, const float* __restrict__ bw,
    const float* __restrict__ bb, const float* __restrict__ bs,
    float* __restrict__ out)
{
    const int bz = blockIdx.z;
    const int c  = bz % C_;
    const int oy0 = blockIdx.y * 32, ox0 = blockIdx.x * 32;

    __shared__ float sX[36][38];        // stride 38 (even) for float2 windows
    __shared__ float sC0[4][16][17];
    __shared__ float sC1[4][8][9];
    __shared__ float sC2[4][4][5];
    __shared__ float sW[25];

    const int tid = threadIdx.x;
    if (tid < 25) sW[tid] = bw[c * 25 + tid];

    // input tile with halo 2 (224 % 32 == 0: interior tiles need no pad,
    // edges zero-padded)
    const float* xp = x + (size_t)bz * H_ * W_;
    const int iy0 = oy0 - 2, ix0 = ox0 - 2;
    for (int i = tid; i < 36 * 36; i += 256) {
        int r = i / 36, cc = i % 36;
        int gy = iy0 + r, gx = ix0 + cc;
        sX[r][cc] = (gy >= 0 && gy < H_ && gx >= 0 && gx < W_) ? xp[(size_t)gy * W_ + gx] : 0.f;
    }

    // coefficient tiles (no halo needed; all aligned to tile boundaries)
    {
        const int cy0 = blockIdx.y * 16, cx0 = blockIdx.x * 16;
        const float* cp = g_arena + OFF_C0 + (size_t)bz * 4 * 112 * 112;
        for (int i = tid; i < 4 * 16 * 16; i += 256) {
            int s = i >> 8, r = (i >> 4) & 15, cc = i & 15;
            sC0[s][r][cc] = cp[((size_t)s * 112 + cy0 + r) * 112 + cx0 + cc];
        }
        const float* c1p = g_arena + OFF_C1 + (size_t)bz * 4 * 56 * 56;
        {   // 256 elems: one per thread
            int s = tid >> 6, r = (tid >> 3) & 7, cc = tid & 7;
            sC1[s][r][cc] = c1p[((size_t)s * 56 + blockIdx.y * 8 + r) * 56 + blockIdx.x * 8 + cc];
        }
        if (tid < 64) {
            const float* c2p = g_arena + OFF_C2 + (size_t)bz * 4 * 28 * 28;
            int s = tid >> 4, r = (tid >> 2) & 3, cc = tid & 3;
            sC2[s][r][cc] = c2p[((size_t)s * 28 + blockIdx.y * 4 + r) * 28 + blockIdx.x * 4 + cc];
        }
    }
    __syncthreads();

    const int ty = tid >> 4, tx = tid & 15;

    // base depthwise conv: 2x2 quad, conflict-free float2 window
    float wreg[6][6];
    #pragma unroll
    for (int r = 0; r < 6; r++) {
        float2 p0 = *(const float2*)&sX[2 * ty + r][2 * tx];
        float2 p1 = *(const float2*)&sX[2 * ty + r][2 * tx + 2];
        float2 p2 = *(const float2*)&sX[2 * ty + r][2 * tx + 4];
        wreg[r][0] = p0.x; wreg[r][1] = p0.y;
        wreg[r][2] = p1.x; wreg[r][3] = p1.y;
        wreg[r][4] = p2.x; wreg[r][5] = p2.y;
    }
    float a00 = 0.f, a01 = 0.f, a10 = 0.f, a11 = 0.f;
    #pragma unroll
    for (int ky = 0; ky < 5; ky++)
        #pragma unroll
        for (int kx = 0; kx < 5; kx++) {
            float wt = sW[ky * 5 + kx];
            a00 = fmaf(wreg[ky][kx],     wt, a00);
            a01 = fmaf(wreg[ky][kx + 1], wt, a01);
            a10 = fmaf(wreg[ky + 1][kx],     wt, a10);
            a11 = fmaf(wreg[ky + 1][kx + 1], wt, a11);
        }

    // inverse chain: c2 -> rec2 -> c1 -> rec1 -> c0 -> output quad
    const int y1 = ty >> 1, x1 = tx >> 1;
    const int y2 = ty >> 2, x2 = tx >> 2;

    float fx2 = (x1 & 1) ? -1.f : 1.f, fy2 = (y1 & 1) ? -1.f : 1.f;
    float rec2 = 0.5f * (sC2[0][y2][x2] + fx2 * sC2[1][y2][x2]
                       + fy2 * sC2[2][y2][x2] + fx2 * fy2 * sC2[3][y2][x2]);

    float ll1 = sC1[0][y1][x1] + rec2;
    float fx1 = (tx & 1) ? -1.f : 1.f, fy1 = (ty & 1) ? -1.f : 1.f;
    float rec1 = 0.5f * (ll1 + fx1 * sC1[1][y1][x1]
                       + fy1 * sC1[2][y1][x1] + fx1 * fy1 * sC1[3][y1][x1]);

    float ll0 = sC0[0][ty][tx] + rec1;
    float lh0 = sC0[1][ty][tx];
    float hl0 = sC0[2][ty][tx];
    float hh0 = sC0[3][ty][tx];
    float ra = (ll0 + lh0 + hl0 + hh0) * 0.5f;
    float rb = (ll0 - lh0 + hl0 - hh0) * 0.5f;
    float rc = (ll0 + lh0 - hl0 - hh0) * 0.5f;
    float rd = (ll0 - lh0 - hl0 + hh0) * 0.5f;

    float scale = bs[c], bias = bb[c];
    const int oy = oy0 + 2 * ty, ox = ox0 + 2 * tx;
    float* op = out + (size_t)bz * H_ * W_;
    *(float2*)&op[(size_t)oy * W_ + ox] =
        make_float2(fmaf(a00, scale, bias) + ra, fmaf(a01, scale, bias) + rb);
    *(float2*)&op[(size_t)(oy + 1) * W_ + ox] =
        make_float2(fmaf(a10, scale, bias) + rc, fmaf(a11, scale, bias) + rd);
}

// ---------------------------------------------------------------------------
extern "C" void kernel_launch(void* const* d_in, const int* in_sizes, int n_in,
                              void* d_out, int out_size)
{
    const float* x   = (const float*)d_in[0];   // (8,96,224,224)
    const float* bw  = (const float*)d_in[1];   // (96,1,5,5)
    const float* bb  = (const float*)d_in[2];   // (96)
    const float* bs  = (const float*)d_in[3];   // (1,96,1,1)
    const float* wv  = (const float*)d_in[4];   // (3,384,1,5,5)
    const float* sv  = (const float*)d_in[5];   // (3,1,384,1,1)
    float* out = (float*)d_out;

    const int LVL_W = 4 * C_ * 25;
    const int LVL_S = 4 * C_;

    fwd_kernel<<<dim3(4, 4, BC_), 224>>>(x, 1, 0, 224, 224,
                                         wv, sv, OFF_C0, OFF_LL1, 1);
    fwd_kernel<<<dim3(2, 2, BC_), 224>>>(nullptr, 0, OFF_LL1, 112, 112,
                                         wv + LVL_W, sv + LVL_S, OFF_C1, OFF_LL2, 1);
    fwd_kernel<<<dim3(1, 1, BC_), 224>>>(nullptr, 0, OFF_LL2, 56, 56,
                                         wv + 2 * LVL_W, sv + 2 * LVL_S, OFF_C2, 0, 0);

    final_kernel<<<dim3(7, 7, BC_), 256>>>(x, bw, bb, bs, out);
}